// round 3
// baseline (speedup 1.0000x reference)
#include <cuda_runtime.h>
#include <cstdint>

#define NN   50000
#define EE   800000
#define INC  256
#define HIDC 128
#define OUTC 64

// ---- scratch (no allocs allowed -> device globals) ----
__device__ float g_deg[NN];
__device__ float g_dinv[NN];
__device__ int   g_cnt[NN];
__device__ int   g_row_start[NN + 1];
__device__ int   g_fill[NN];
__device__ int   g_csr_src[EE];
__device__ float g_h1[NN * HIDC];
__device__ float g_a1[NN * HIDC];
__device__ float g_h2[NN * OUTC];
__device__ int   g_is64;

// ---- detect whether edge_index is int64 or int32 ----
__global__ void detect_kernel(const int* __restrict__ p) {
    if (threadIdx.x == 0 && blockIdx.x == 0) {
        int ok = 1;
        for (int i = 0; i < 64; i++) {
            int lo = p[2 * i], hi = p[2 * i + 1];
            if (hi != 0 || (unsigned)lo >= (unsigned)NN) { ok = 0; break; }
        }
        g_is64 = ok;
    }
}

__device__ __forceinline__ int edge_at(const void* e, long long pos, int is64) {
    if (is64) return (int)((const long long*)e)[pos];
    return ((const int*)e)[pos];
}

__global__ void init_kernel() {
    int i = blockIdx.x * blockDim.x + threadIdx.x;
    if (i < NN) { g_deg[i] = 1.0f; g_cnt[i] = 0; }   // 1.0 = self loop
}

__global__ void count_kernel(const void* __restrict__ eidx) {
    int e = blockIdx.x * blockDim.x + threadIdx.x;
    if (e < EE) {
        int is64 = g_is64;
        int d = edge_at(eidx, (long long)EE + e, is64);  // row 1 = dst
        atomicAdd(&g_deg[d], 1.0f);
        atomicAdd(&g_cnt[d], 1);
    }
}

__global__ void dinv_kernel() {
    int i = blockIdx.x * blockDim.x + threadIdx.x;
    if (i < NN) g_dinv[i] = rsqrtf(g_deg[i]);
}

// single-block exclusive scan of g_cnt -> g_row_start, also primes g_fill
__global__ void scan_kernel() {
    __shared__ int part[1024];
    int tid = threadIdx.x;
    const int CH = (NN + 1023) / 1024;
    int base = tid * CH;
    int s = 0;
    for (int j = 0; j < CH; j++) { int i = base + j; if (i < NN) s += g_cnt[i]; }
    part[tid] = s;
    __syncthreads();
    for (int off = 1; off < 1024; off <<= 1) {
        int v = (tid >= off) ? part[tid - off] : 0;
        __syncthreads();
        part[tid] += v;
        __syncthreads();
    }
    int run = (tid == 0) ? 0 : part[tid - 1];
    for (int j = 0; j < CH; j++) {
        int i = base + j;
        if (i < NN) { g_row_start[i] = run; g_fill[i] = run; run += g_cnt[i]; }
    }
    if (tid == 0) g_row_start[NN] = EE;
}

__global__ void fill_kernel(const void* __restrict__ eidx) {
    int e = blockIdx.x * blockDim.x + threadIdx.x;
    if (e < EE) {
        int is64 = g_is64;
        int s = edge_at(eidx, (long long)e, is64);        // row 0 = src
        int d = edge_at(eidx, (long long)EE + e, is64);   // row 1 = dst
        int pos = atomicAdd(&g_fill[d], 1);
        g_csr_src[pos] = s;
    }
}

// ============================================================
// 3xTF32 tensor-core GEMM:  C[M,NC] = A[M,KC] @ B[KC,NC]
// A = Ahi + Alo (hi = tf32-truncate, lo exact residual);
// acc = AhiBhi + AhiBlo + AloBhi  -> ~2^-21 relative error.
// smem is staged directly in m16n8k8 fragment layout.
// ============================================================

__device__ __forceinline__ float tf32_trunc(float a) {
    return __uint_as_float(__float_as_uint(a) & 0xFFFFE000u);
}

__device__ __forceinline__ void mma_tf32(float* d, const uint32_t* a, const uint32_t* b) {
    asm volatile(
        "mma.sync.aligned.m16n8k8.row.col.f32.tf32.tf32.f32 "
        "{%0,%1,%2,%3}, {%4,%5,%6,%7}, {%8,%9}, {%0,%1,%2,%3};\n"
        : "+f"(d[0]), "+f"(d[1]), "+f"(d[2]), "+f"(d[3])
        : "r"(a[0]), "r"(a[1]), "r"(a[2]), "r"(a[3]), "r"(b[0]), "r"(b[1]));
}

template <int KC, int NC, int WARPS_M, int WARPS_N>
__global__ void __launch_bounds__(256, 1) mma_gemm_kernel(
    const float* __restrict__ A, const float* __restrict__ B,
    float* __restrict__ C, int M)
{
    constexpr int BM = 128, BK = 16;
    constexpr int NT  = NC / 8;          // n8 tiles per block
    constexpr int WM  = BM / WARPS_M;    // warp tile M
    constexpr int MT  = WM / 16;         // m16 tiles per warp
    constexpr int WNT = NT / WARPS_N;    // n8 tiles per warp
    static_assert(WNT == 4, "warp n-tiles fixed at 4");

    // frag layout: [hi/lo][k8][tile][lane][regs]
    __shared__ alignas(16) float As[2][BK / 8][BM / 16][32][4];
    __shared__ alignas(16) float Bs[2][BK / 8][NT][32][2];

    int tid  = threadIdx.x;
    int wid  = tid >> 5, lane = tid & 31;
    int warp_m = wid % WARPS_M;
    int warp_n = wid / WARPS_M;
    int bm = blockIdx.x * BM;

    float acc[MT][4][4];
    #pragma unroll
    for (int im = 0; im < MT; im++)
        #pragma unroll
        for (int in_ = 0; in_ < 4; in_++)
            #pragma unroll
            for (int r = 0; r < 4; r++) acc[im][in_][r] = 0.f;

    for (int k0 = 0; k0 < KC; k0 += BK) {
        // ---- stage A tile (BM x BK) into frag layout, hi/lo split ----
        constexpr int AF4 = (BM * BK / 4) / 256;   // float4 loads per thread
        #pragma unroll
        for (int i = 0; i < AF4; i++) {
            int f   = tid + i * 256;
            int row = f / (BK / 4);
            int q   = f % (BK / 4);                // which float4 within row
            float4 v = make_float4(0.f, 0.f, 0.f, 0.f);
            if (bm + row < M)
                v = *(const float4*)(A + (size_t)(bm + row) * KC + k0 + q * 4);
            int k8    = q >> 1;
            int chalf = q & 1;                     // cols 0-3 vs 4-7 of the k8
            int rr = row & 15, mt = row >> 4;
            int regb  = chalf * 2 + (rr >> 3);     // a0..a3 index
            int lane0 = (rr & 7) * 4;
            float* hp = &As[0][k8][mt][0][0];
            float* lp = &As[1][k8][mt][0][0];
            float e[4] = {v.x, v.y, v.z, v.w};
            #pragma unroll
            for (int j = 0; j < 4; j++) {
                float hi = tf32_trunc(e[j]);
                hp[(lane0 + j) * 4 + regb] = hi;
                lp[(lane0 + j) * 4 + regb] = e[j] - hi;
            }
        }
        // ---- stage B tile (BK x NC) into frag layout, hi/lo split ----
        constexpr int BF4 = (BK * NC / 4) / 256;
        #pragma unroll
        for (int i = 0; i < BF4; i++) {
            int f    = tid + i * 256;
            int krow = f / (NC / 4);
            int q    = f % (NC / 4);
            float4 v = *(const float4*)(B + (size_t)(k0 + krow) * NC + q * 4);
            int k8 = krow >> 3;
            int rr = krow & 7;
            int regb = rr >> 2;                    // b0 / b1
            int lr   = rr & 3;
            int n0 = q * 4;
            int nt = n0 >> 3;
            int c0 = n0 & 7;
            float* hp = &Bs[0][k8][nt][0][0];
            float* lp = &Bs[1][k8][nt][0][0];
            float e[4] = {v.x, v.y, v.z, v.w};
            #pragma unroll
            for (int j = 0; j < 4; j++) {
                int lanej = (c0 + j) * 4 + lr;
                float hi = tf32_trunc(e[j]);
                hp[lanej * 2 + regb] = hi;
                lp[lanej * 2 + regb] = e[j] - hi;
            }
        }
        __syncthreads();

        // ---- compute ----
        #pragma unroll
        for (int k8 = 0; k8 < BK / 8; k8++) {
            uint32_t ah[MT][4], al[MT][4], bh[4][2], bl[4][2];
            #pragma unroll
            for (int im = 0; im < MT; im++) {
                uint4 th = *(const uint4*)&As[0][k8][warp_m * MT + im][lane][0];
                ah[im][0] = th.x; ah[im][1] = th.y; ah[im][2] = th.z; ah[im][3] = th.w;
                uint4 tl = *(const uint4*)&As[1][k8][warp_m * MT + im][lane][0];
                al[im][0] = tl.x; al[im][1] = tl.y; al[im][2] = tl.z; al[im][3] = tl.w;
            }
            #pragma unroll
            for (int in_ = 0; in_ < 4; in_++) {
                uint2 th = *(const uint2*)&Bs[0][k8][warp_n * 4 + in_][lane][0];
                bh[in_][0] = th.x; bh[in_][1] = th.y;
                uint2 tl = *(const uint2*)&Bs[1][k8][warp_n * 4 + in_][lane][0];
                bl[in_][0] = tl.x; bl[in_][1] = tl.y;
            }
            #pragma unroll
            for (int im = 0; im < MT; im++)
                #pragma unroll
                for (int in_ = 0; in_ < 4; in_++) {
                    mma_tf32(acc[im][in_], ah[im], bh[in_]);
                    mma_tf32(acc[im][in_], ah[im], bl[in_]);
                    mma_tf32(acc[im][in_], al[im], bh[in_]);
                }
        }
        __syncthreads();
    }

    // ---- epilogue ----
    int g = lane >> 2, tg = lane & 3;
    #pragma unroll
    for (int im = 0; im < MT; im++) {
        #pragma unroll
        for (int in_ = 0; in_ < 4; in_++) {
            int m0 = bm + warp_m * WM + im * 16 + g;
            int n  = (warp_n * 4 + in_) * 8 + tg * 2;
            if (m0 < M)
                *(float2*)(C + (size_t)m0 * NC + n) =
                    make_float2(acc[im][in_][0], acc[im][in_][1]);
            if (m0 + 8 < M)
                *(float2*)(C + (size_t)(m0 + 8) * NC + n) =
                    make_float2(acc[im][in_][2], acc[im][in_][3]);
        }
    }
}

// ---- CSR aggregation: one warp per destination node, atomic-free ----
template <int C, bool RELU>
__global__ void __launch_bounds__(256) agg_kernel(
    const float* __restrict__ hin, const float* __restrict__ bias,
    float* __restrict__ out)
{
    int gw   = (blockIdx.x * blockDim.x + threadIdx.x) >> 5;
    int lane = threadIdx.x & 31;
    if (gw >= NN) return;
    constexpr int V = C / 32;

    float dv = g_dinv[gw];
    float acc[V];
    {   // self loop
        float w = dv * dv;
        const float* hr = hin + (size_t)gw * C + lane * V;
        if constexpr (V == 4) {
            float4 v = *(const float4*)hr;
            acc[0] = v.x * w; acc[1] = v.y * w; acc[2] = v.z * w; acc[3] = v.w * w;
        } else {
            float2 v = *(const float2*)hr;
            acc[0] = v.x * w; acc[1] = v.y * w;
        }
    }

    int beg = g_row_start[gw], end = g_row_start[gw + 1];
    for (int e = beg; e < end; e++) {
        int s = g_csr_src[e];
        float w = dv * g_dinv[s];
        const float* hs = hin + (size_t)s * C + lane * V;
        if constexpr (V == 4) {
            float4 v = *(const float4*)hs;
            acc[0] += v.x * w; acc[1] += v.y * w; acc[2] += v.z * w; acc[3] += v.w * w;
        } else {
            float2 v = *(const float2*)hs;
            acc[0] += v.x * w; acc[1] += v.y * w;
        }
    }

    const float* bp = bias + lane * V;
    float* op = out + (size_t)gw * C + lane * V;
    if constexpr (V == 4) {
        float4 b = *(const float4*)bp;
        float4 o = make_float4(acc[0] + b.x, acc[1] + b.y, acc[2] + b.z, acc[3] + b.w);
        if (RELU) {
            o.x = fmaxf(o.x, 0.f); o.y = fmaxf(o.y, 0.f);
            o.z = fmaxf(o.z, 0.f); o.w = fmaxf(o.w, 0.f);
        }
        *(float4*)op = o;
    } else {
        float2 b = *(const float2*)bp;
        float2 o = make_float2(acc[0] + b.x, acc[1] + b.y);
        if (RELU) { o.x = fmaxf(o.x, 0.f); o.y = fmaxf(o.y, 0.f); }
        *(float2*)op = o;
    }
}

extern "C" void kernel_launch(void* const* d_in, const int* in_sizes, int n_in,
                              void* d_out, int out_size)
{
    const float* x  = (const float*)d_in[0];
    const void*  ei = d_in[1];
    const float* W1 = (const float*)d_in[2];
    const float* b1 = (const float*)d_in[3];
    const float* W2 = (const float*)d_in[4];
    const float* b2 = (const float*)d_in[5];
    float* out = (float*)d_out;

    float *h1, *a1, *h2;
    cudaGetSymbolAddress((void**)&h1, g_h1);
    cudaGetSymbolAddress((void**)&a1, g_a1);
    cudaGetSymbolAddress((void**)&h2, g_h2);

    const int NB = (NN + 255) / 256;
    const int EB = (EE + 255) / 256;

    detect_kernel<<<1, 32>>>((const int*)ei);
    init_kernel<<<NB, 256>>>();
    count_kernel<<<EB, 256>>>(ei);
    dinv_kernel<<<NB, 256>>>();
    scan_kernel<<<1, 1024>>>();
    fill_kernel<<<EB, 256>>>(ei);

    const int GB = (NN + 127) / 128;

    // layer 1: h1 = x @ W1 ; a1 = relu(agg(h1) + b1)
    mma_gemm_kernel<INC, HIDC, 2, 4><<<GB, 256>>>(x, W1, h1, NN);
    agg_kernel<HIDC, true><<<(NN * 32 + 255) / 256, 256>>>(h1, b1, a1);

    // layer 2: h2 = a1 @ W2 ; out = agg(h2) + b2
    mma_gemm_kernel<HIDC, OUTC, 4, 2><<<GB, 256>>>(a1, W2, h2, NN);
    agg_kernel<OUTC, false><<<(NN * 32 + 255) / 256, 256>>>(h2, b2, out);
}

// round 7
// speedup vs baseline: 1.5105x; 1.5105x over previous
#include <cuda_runtime.h>
#include <cstdint>

#define NN   50000
#define EE   800000
#define INC  256
#define HIDC 128
#define OUTC 64

typedef unsigned long long ull;

// ---- scratch (no allocs allowed -> device globals) ----
__device__ float g_dinv[NN];
__device__ int   g_cnt[NN];
__device__ int   g_row_start[NN + 1];
__device__ int   g_fill[NN];
__device__ int   g_csr_src[EE];
__device__ float g_h1[NN * HIDC];
__device__ float g_a1[NN * HIDC];
__device__ float g_h2[NN * OUTC];
__device__ int   g_is64;

// ---- detect whether edge_index is int64 or int32 ----
__global__ void detect_kernel(const int* __restrict__ p) {
    if (threadIdx.x == 0 && blockIdx.x == 0) {
        int ok = 1;
        for (int i = 0; i < 64; i++) {
            int lo = p[2 * i], hi = p[2 * i + 1];
            if (hi != 0 || (unsigned)lo >= (unsigned)NN) { ok = 0; break; }
        }
        g_is64 = ok;
    }
}

__device__ __forceinline__ int edge_at(const void* e, long long pos, int is64) {
    if (is64) return (int)((const long long*)e)[pos];
    return ((const int*)e)[pos];
}

__global__ void count_kernel(const void* __restrict__ eidx) {
    int e = blockIdx.x * blockDim.x + threadIdx.x;
    if (e < EE) {
        int is64 = g_is64;
        int d = edge_at(eidx, (long long)EE + e, is64);  // row 1 = dst
        atomicAdd(&g_cnt[d], 1);
    }
}

__global__ void dinv_kernel() {
    int i = blockIdx.x * blockDim.x + threadIdx.x;
    if (i < NN) g_dinv[i] = rsqrtf((float)(g_cnt[i] + 1));  // +1 = self loop
}

// single-block exclusive scan of g_cnt -> g_row_start, also primes g_fill
__global__ void scan_kernel() {
    __shared__ int part[1024];
    int tid = threadIdx.x;
    const int CH = (NN + 1023) / 1024;
    int base = tid * CH;
    int s = 0;
    for (int j = 0; j < CH; j++) { int i = base + j; if (i < NN) s += g_cnt[i]; }
    part[tid] = s;
    __syncthreads();
    for (int off = 1; off < 1024; off <<= 1) {
        int v = (tid >= off) ? part[tid - off] : 0;
        __syncthreads();
        part[tid] += v;
        __syncthreads();
    }
    int run = (tid == 0) ? 0 : part[tid - 1];
    for (int j = 0; j < CH; j++) {
        int i = base + j;
        if (i < NN) { g_row_start[i] = run; g_fill[i] = run; run += g_cnt[i]; }
    }
    if (tid == 0) g_row_start[NN] = EE;
}

__global__ void fill_kernel(const void* __restrict__ eidx) {
    int e = blockIdx.x * blockDim.x + threadIdx.x;
    if (e < EE) {
        int is64 = g_is64;
        int s = edge_at(eidx, (long long)e, is64);        // row 0 = src
        int d = edge_at(eidx, (long long)EE + e, is64);   // row 1 = dst
        int pos = atomicAdd(&g_fill[d], 1);
        g_csr_src[pos] = s;
    }
}

// ---- packed-f32x2 helpers ----
__device__ __forceinline__ ull pack2(float x, float y) {
    ull r; asm("mov.b64 %0, {%1, %2};" : "=l"(r) : "f"(x), "f"(y)); return r;
}
__device__ __forceinline__ void unpack2(ull v, float& x, float& y) {
    asm("mov.b64 {%0, %1}, %2;" : "=f"(x), "=f"(y) : "l"(v));
}
__device__ __forceinline__ void ffma2(ull& d, ull a, ull b) {
    asm("fma.rn.f32x2 %0, %1, %2, %0;" : "+l"(d) : "l"(a), "l"(b));
}

// ---- tiled fp32 GEMM with packed FFMA2: C[M,NC] = A[M,KC] @ B[KC,NC] ----
// Thread tile: RPT rows x 4 cols, rows paired into f32x2 lanes.
// A smem reads are warp-uniform (broadcast); B smem reads are LDS.128 conflict-free.
template <int KC, int NC>
__global__ void __launch_bounds__(256) gemm_kernel(
    const float* __restrict__ A, const float* __restrict__ B,
    float* __restrict__ C, int M)
{
    constexpr int TM = 64, TK = 16;
    constexpr int CG = NC / 4;         // threads along N      (32 / 16)
    constexpr int RG = 256 / CG;       // thread rows          (8 / 16)
    constexpr int RPT = TM / RG;       // rows per thread      (8 / 4)
    constexpr int RP2 = RPT / 2;       // f32x2 row pairs      (4 / 2)
    constexpr int BV = (TK * NC / 4) / 256;  // B float4 per thread (2 / 1)

    __shared__ float As[TK][TM + 8];   // transposed A tile; +8 keeps 8B align
    __shared__ float Bs[TK][NC];

    int tid  = threadIdx.x;
    int tx   = tid % CG;
    int ty   = tid / CG;
    int row0 = ty * RPT;               // even -> 8B-aligned float2 smem reads
    int col  = tx * 4;
    int bm   = blockIdx.x * TM;

    int am  = tid >> 2;                // A row within tile (0..63)
    int akq = tid & 3;                 // which float4 of the 16 K-cols

    ull acc[RP2][4];
    #pragma unroll
    for (int r = 0; r < RP2; r++)
        #pragma unroll
        for (int c = 0; c < 4; c++) acc[r][c] = 0ull;  // bits(0,0) = (+0.f,+0.f)

    // ---- prefetch chunk 0 into registers ----
    float4 av = make_float4(0.f, 0.f, 0.f, 0.f);
    if (bm + am < M)
        av = *(const float4*)(A + (size_t)(bm + am) * KC + akq * 4);
    float4 bvp[BV];
    #pragma unroll
    for (int i = 0; i < BV; i++) {
        int idx = tid + i * 256;
        int bk = idx / (NC / 4);
        int bc = (idx % (NC / 4)) * 4;
        bvp[i] = *(const float4*)(B + (size_t)bk * NC + bc);
    }

    constexpr int NCH = KC / TK;
    #pragma unroll 1
    for (int ch = 0; ch < NCH; ch++) {
        // ---- store staged regs to smem ----
        As[akq * 4 + 0][am] = av.x;
        As[akq * 4 + 1][am] = av.y;
        As[akq * 4 + 2][am] = av.z;
        As[akq * 4 + 3][am] = av.w;
        #pragma unroll
        for (int i = 0; i < BV; i++) {
            int idx = tid + i * 256;
            int bk = idx / (NC / 4);
            int bc = (idx % (NC / 4)) * 4;
            *(float4*)&Bs[bk][bc] = bvp[i];
        }
        __syncthreads();

        // ---- prefetch next chunk ----
        if (ch + 1 < NCH) {
            int k0 = (ch + 1) * TK;
            av = make_float4(0.f, 0.f, 0.f, 0.f);
            if (bm + am < M)
                av = *(const float4*)(A + (size_t)(bm + am) * KC + k0 + akq * 4);
            #pragma unroll
            for (int i = 0; i < BV; i++) {
                int idx = tid + i * 256;
                int bk = idx / (NC / 4);
                int bc = (idx % (NC / 4)) * 4;
                bvp[i] = *(const float4*)(B + (size_t)(k0 + bk) * NC + bc);
            }
        }

        // ---- compute ----
        #pragma unroll
        for (int k = 0; k < TK; k++) {
            float4 b = *(const float4*)&Bs[k][col];
            ull b2[4];
            b2[0] = pack2(b.x, b.x);
            b2[1] = pack2(b.y, b.y);
            b2[2] = pack2(b.z, b.z);
            b2[3] = pack2(b.w, b.w);
            const ull* ap = (const ull*)&As[k][row0];  // warp-uniform -> broadcast
            #pragma unroll
            for (int r = 0; r < RP2; r++) {
                ull a2 = ap[r];
                ffma2(acc[r][0], a2, b2[0]);
                ffma2(acc[r][1], a2, b2[1]);
                ffma2(acc[r][2], a2, b2[2]);
                ffma2(acc[r][3], a2, b2[3]);
            }
        }
        __syncthreads();
    }

    // ---- epilogue: unpack pairs, store two rows per pair ----
    #pragma unroll
    for (int r = 0; r < RP2; r++) {
        float lo[4], hi[4];
        #pragma unroll
        for (int c = 0; c < 4; c++) unpack2(acc[r][c], lo[c], hi[c]);
        int m0 = bm + row0 + 2 * r;
        if (m0 < M)
            *(float4*)(C + (size_t)m0 * NC + col) =
                make_float4(lo[0], lo[1], lo[2], lo[3]);
        if (m0 + 1 < M)
            *(float4*)(C + (size_t)(m0 + 1) * NC + col) =
                make_float4(hi[0], hi[1], hi[2], hi[3]);
    }
}

// ---- CSR aggregation: one warp per destination node, atomic-free ----
template <int C, bool RELU>
__global__ void __launch_bounds__(256) agg_kernel(
    const float* __restrict__ hin, const float* __restrict__ bias,
    float* __restrict__ out)
{
    int gw   = (blockIdx.x * blockDim.x + threadIdx.x) >> 5;
    int lane = threadIdx.x & 31;
    if (gw >= NN) return;
    constexpr int V = C / 32;

    float dv = g_dinv[gw];
    float acc[V];
    {   // self loop
        float w = dv * dv;
        const float* hr = hin + (size_t)gw * C + lane * V;
        if constexpr (V == 4) {
            float4 v = *(const float4*)hr;
            acc[0] = v.x * w; acc[1] = v.y * w; acc[2] = v.z * w; acc[3] = v.w * w;
        } else {
            float2 v = *(const float2*)hr;
            acc[0] = v.x * w; acc[1] = v.y * w;
        }
    }

    int beg = g_row_start[gw], end = g_row_start[gw + 1];
    for (int e = beg; e < end; e++) {
        int s = g_csr_src[e];
        float w = dv * g_dinv[s];
        const float* hs = hin + (size_t)s * C + lane * V;
        if constexpr (V == 4) {
            float4 v = *(const float4*)hs;
            acc[0] += v.x * w; acc[1] += v.y * w; acc[2] += v.z * w; acc[3] += v.w * w;
        } else {
            float2 v = *(const float2*)hs;
            acc[0] += v.x * w; acc[1] += v.y * w;
        }
    }

    const float* bp = bias + lane * V;
    float* op = out + (size_t)gw * C + lane * V;
    if constexpr (V == 4) {
        float4 b = *(const float4*)bp;
        float4 o = make_float4(acc[0] + b.x, acc[1] + b.y, acc[2] + b.z, acc[3] + b.w);
        if (RELU) {
            o.x = fmaxf(o.x, 0.f); o.y = fmaxf(o.y, 0.f);
            o.z = fmaxf(o.z, 0.f); o.w = fmaxf(o.w, 0.f);
        }
        *(float4*)op = o;
    } else {
        float2 b = *(const float2*)bp;
        float2 o = make_float2(acc[0] + b.x, acc[1] + b.y);
        if (RELU) { o.x = fmaxf(o.x, 0.f); o.y = fmaxf(o.y, 0.f); }
        *(float2*)op = o;
    }
}

extern "C" void kernel_launch(void* const* d_in, const int* in_sizes, int n_in,
                              void* d_out, int out_size)
{
    const float* x  = (const float*)d_in[0];
    const void*  ei = d_in[1];
    const float* W1 = (const float*)d_in[2];
    const float* b1 = (const float*)d_in[3];
    const float* W2 = (const float*)d_in[4];
    const float* b2 = (const float*)d_in[5];
    float* out = (float*)d_out;

    float *h1, *a1, *h2;
    int* cnt;
    cudaGetSymbolAddress((void**)&h1, g_h1);
    cudaGetSymbolAddress((void**)&a1, g_a1);
    cudaGetSymbolAddress((void**)&h2, g_h2);
    cudaGetSymbolAddress((void**)&cnt, g_cnt);

    const int NB = (NN + 255) / 256;
    const int EB = (EE + 255) / 256;

    detect_kernel<<<1, 32>>>((const int*)ei);
    cudaMemsetAsync(cnt, 0, NN * sizeof(int));
    count_kernel<<<EB, 256>>>(ei);
    dinv_kernel<<<NB, 256>>>();
    scan_kernel<<<1, 1024>>>();
    fill_kernel<<<EB, 256>>>(ei);

    // layer 1: h1 = x @ W1 ; a1 = relu(agg(h1) + b1)
    gemm_kernel<INC, HIDC><<<(NN + 63) / 64, 256>>>(x, W1, h1, NN);
    agg_kernel<HIDC, true><<<(NN * 32 + 255) / 256, 256>>>(h1, b1, a1);

    // layer 2: h2 = a1 @ W2 ; out = agg(h2) + b2
    gemm_kernel<HIDC, OUTC><<<(NN + 63) / 64, 256>>>(a1, W2, h2, NN);
    agg_kernel<OUTC, false><<<(NN * 32 + 255) / 256, 256>>>(h2, b2, out);
}

// round 8
// speedup vs baseline: 2.0832x; 1.3791x over previous
#include <cuda_runtime.h>
#include <cstdint>

#define NN   50000
#define EE   800000
#define INC  256
#define HIDC 128
#define OUTC 64

#define SCAN_B 196            // scan blocks (196*256 = 50176 >= NN)

typedef unsigned long long ull;

// ---- scratch (no allocs allowed -> device globals) ----
__device__ float g_dinv[NN];
__device__ int   g_cnt[NN];
__device__ int   g_row_start[NN + 1];
__device__ int   g_fill[NN];
__device__ int   g_csr_src[EE];
__device__ int   g_bsum[SCAN_B];
__device__ int   g_boff[SCAN_B];
__device__ float g_h1[NN * HIDC];
__device__ float g_a1[NN * HIDC];
__device__ float g_h2[NN * OUTC];
__device__ int   g_is64;

// ---- detect whether edge_index is int64 or int32 ----
__global__ void detect_kernel(const int* __restrict__ p) {
    if (threadIdx.x == 0 && blockIdx.x == 0) {
        int ok = 1;
        for (int i = 0; i < 64; i++) {
            int lo = p[2 * i], hi = p[2 * i + 1];
            if (hi != 0 || (unsigned)lo >= (unsigned)NN) { ok = 0; break; }
        }
        g_is64 = ok;
    }
}

__device__ __forceinline__ int edge_at(const void* e, long long pos, int is64) {
    if (is64) return (int)((const long long*)e)[pos];
    return ((const int*)e)[pos];
}

__global__ void count_kernel(const void* __restrict__ eidx) {
    int e = blockIdx.x * blockDim.x + threadIdx.x;
    if (e < EE) {
        int is64 = g_is64;
        int d = edge_at(eidx, (long long)EE + e, is64);  // row 1 = dst
        atomicAdd(&g_cnt[d], 1);
    }
}

// ===== 3-phase parallel scan of g_cnt -> g_row_start (+ g_fill, g_dinv) =====

// phase 1: per-block sums
__global__ void __launch_bounds__(256) bsum_kernel() {
    __shared__ int wsum[8];
    int i = blockIdx.x * 256 + threadIdx.x;
    int v = (i < NN) ? g_cnt[i] : 0;
    int s = v;
    #pragma unroll
    for (int o = 16; o > 0; o >>= 1) s += __shfl_down_sync(0xffffffffu, s, o);
    int lane = threadIdx.x & 31, w = threadIdx.x >> 5;
    if (lane == 0) wsum[w] = s;
    __syncthreads();
    if (w == 0) {
        int t = (lane < 8) ? wsum[lane] : 0;
        #pragma unroll
        for (int o = 4; o > 0; o >>= 1) t += __shfl_down_sync(0xffffffffu, t, o);
        if (lane == 0) g_bsum[blockIdx.x] = t;
    }
}

// phase 2: exclusive scan of SCAN_B block sums (one block)
__global__ void __launch_bounds__(256) bscan_kernel() {
    __shared__ int wtot[8];
    int tid = threadIdx.x;
    int v = (tid < SCAN_B) ? g_bsum[tid] : 0;
    int lane = tid & 31, w = tid >> 5;
    int inc = v;
    #pragma unroll
    for (int o = 1; o < 32; o <<= 1) {
        int t = __shfl_up_sync(0xffffffffu, inc, o);
        if (lane >= o) inc += t;
    }
    if (lane == 31) wtot[w] = inc;
    __syncthreads();
    int wo = 0;
    #pragma unroll
    for (int j = 0; j < 8; j++) if (j < w) wo += wtot[j];
    if (tid < SCAN_B) g_boff[tid] = wo + inc - v;   // exclusive
}

// phase 3: block-local exclusive scan + block offset; fused dinv
__global__ void __launch_bounds__(256) emit_kernel() {
    __shared__ int wtot[8];
    int tid = threadIdx.x;
    int i = blockIdx.x * 256 + tid;
    int v = (i < NN) ? g_cnt[i] : 0;
    int lane = tid & 31, w = tid >> 5;
    int inc = v;
    #pragma unroll
    for (int o = 1; o < 32; o <<= 1) {
        int t = __shfl_up_sync(0xffffffffu, inc, o);
        if (lane >= o) inc += t;
    }
    if (lane == 31) wtot[w] = inc;
    __syncthreads();
    int wo = 0;
    #pragma unroll
    for (int j = 0; j < 8; j++) if (j < w) wo += wtot[j];
    if (i < NN) {
        int excl = g_boff[blockIdx.x] + wo + inc - v;
        g_row_start[i] = excl;
        g_fill[i] = excl;
        g_dinv[i] = rsqrtf((float)(v + 1));          // +1 = self loop
    }
    if (i == 0) g_row_start[NN] = EE;
}

__global__ void fill_kernel(const void* __restrict__ eidx) {
    int e = blockIdx.x * blockDim.x + threadIdx.x;
    if (e < EE) {
        int is64 = g_is64;
        int s = edge_at(eidx, (long long)e, is64);        // row 0 = src
        int d = edge_at(eidx, (long long)EE + e, is64);   // row 1 = dst
        int pos = atomicAdd(&g_fill[d], 1);
        g_csr_src[pos] = s;
    }
}

// ---- packed-f32x2 helpers ----
__device__ __forceinline__ ull pack2(float x, float y) {
    ull r; asm("mov.b64 %0, {%1, %2};" : "=l"(r) : "f"(x), "f"(y)); return r;
}
__device__ __forceinline__ void unpack2(ull v, float& x, float& y) {
    asm("mov.b64 {%0, %1}, %2;" : "=f"(x), "=f"(y) : "l"(v));
}
__device__ __forceinline__ void ffma2(ull& d, ull a, ull b) {
    asm("fma.rn.f32x2 %0, %1, %2, %0;" : "+l"(d) : "l"(a), "l"(b));
}

// ---- tiled fp32 GEMM with packed FFMA2: C[M,NC] = A[M,KC] @ B[KC,NC] ----
template <int KC, int NC>
__global__ void __launch_bounds__(256) gemm_kernel(
    const float* __restrict__ A, const float* __restrict__ B,
    float* __restrict__ C, int M)
{
    constexpr int TM = 64, TK = 16;
    constexpr int CG = NC / 4;
    constexpr int RG = 256 / CG;
    constexpr int RPT = TM / RG;
    constexpr int RP2 = RPT / 2;
    constexpr int BV = (TK * NC / 4) / 256;

    __shared__ float As[TK][TM + 8];
    __shared__ float Bs[TK][NC];

    int tid  = threadIdx.x;
    int tx   = tid % CG;
    int ty   = tid / CG;
    int row0 = ty * RPT;
    int col  = tx * 4;
    int bm   = blockIdx.x * TM;

    int am  = tid >> 2;
    int akq = tid & 3;

    ull acc[RP2][4];
    #pragma unroll
    for (int r = 0; r < RP2; r++)
        #pragma unroll
        for (int c = 0; c < 4; c++) acc[r][c] = 0ull;

    float4 av = make_float4(0.f, 0.f, 0.f, 0.f);
    if (bm + am < M)
        av = *(const float4*)(A + (size_t)(bm + am) * KC + akq * 4);
    float4 bvp[BV];
    #pragma unroll
    for (int i = 0; i < BV; i++) {
        int idx = tid + i * 256;
        int bk = idx / (NC / 4);
        int bc = (idx % (NC / 4)) * 4;
        bvp[i] = *(const float4*)(B + (size_t)bk * NC + bc);
    }

    constexpr int NCH = KC / TK;
    #pragma unroll 1
    for (int ch = 0; ch < NCH; ch++) {
        As[akq * 4 + 0][am] = av.x;
        As[akq * 4 + 1][am] = av.y;
        As[akq * 4 + 2][am] = av.z;
        As[akq * 4 + 3][am] = av.w;
        #pragma unroll
        for (int i = 0; i < BV; i++) {
            int idx = tid + i * 256;
            int bk = idx / (NC / 4);
            int bc = (idx % (NC / 4)) * 4;
            *(float4*)&Bs[bk][bc] = bvp[i];
        }
        __syncthreads();

        if (ch + 1 < NCH) {
            int k0 = (ch + 1) * TK;
            av = make_float4(0.f, 0.f, 0.f, 0.f);
            if (bm + am < M)
                av = *(const float4*)(A + (size_t)(bm + am) * KC + k0 + akq * 4);
            #pragma unroll
            for (int i = 0; i < BV; i++) {
                int idx = tid + i * 256;
                int bk = idx / (NC / 4);
                int bc = (idx % (NC / 4)) * 4;
                bvp[i] = *(const float4*)(B + (size_t)(k0 + bk) * NC + bc);
            }
        }

        #pragma unroll
        for (int k = 0; k < TK; k++) {
            float4 b = *(const float4*)&Bs[k][col];
            ull b2[4];
            b2[0] = pack2(b.x, b.x);
            b2[1] = pack2(b.y, b.y);
            b2[2] = pack2(b.z, b.z);
            b2[3] = pack2(b.w, b.w);
            const ull* ap = (const ull*)&As[k][row0];
            #pragma unroll
            for (int r = 0; r < RP2; r++) {
                ull a2 = ap[r];
                ffma2(acc[r][0], a2, b2[0]);
                ffma2(acc[r][1], a2, b2[1]);
                ffma2(acc[r][2], a2, b2[2]);
                ffma2(acc[r][3], a2, b2[3]);
            }
        }
        __syncthreads();
    }

    #pragma unroll
    for (int r = 0; r < RP2; r++) {
        float lo[4], hi[4];
        #pragma unroll
        for (int c = 0; c < 4; c++) unpack2(acc[r][c], lo[c], hi[c]);
        int m0 = bm + row0 + 2 * r;
        if (m0 < M)
            *(float4*)(C + (size_t)m0 * NC + col) =
                make_float4(lo[0], lo[1], lo[2], lo[3]);
        if (m0 + 1 < M)
            *(float4*)(C + (size_t)(m0 + 1) * NC + col) =
                make_float4(hi[0], hi[1], hi[2], hi[3]);
    }
}

// ---- CSR aggregation: one warp per destination node, atomic-free ----
template <int C, bool RELU>
__global__ void __launch_bounds__(256) agg_kernel(
    const float* __restrict__ hin, const float* __restrict__ bias,
    float* __restrict__ out)
{
    int gw   = (blockIdx.x * blockDim.x + threadIdx.x) >> 5;
    int lane = threadIdx.x & 31;
    if (gw >= NN) return;
    constexpr int V = C / 32;

    float dv = g_dinv[gw];
    float acc[V];
    {   // self loop
        float w = dv * dv;
        const float* hr = hin + (size_t)gw * C + lane * V;
        if constexpr (V == 4) {
            float4 v = *(const float4*)hr;
            acc[0] = v.x * w; acc[1] = v.y * w; acc[2] = v.z * w; acc[3] = v.w * w;
        } else {
            float2 v = *(const float2*)hr;
            acc[0] = v.x * w; acc[1] = v.y * w;
        }
    }

    int beg = g_row_start[gw], end = g_row_start[gw + 1];
    for (int e = beg; e < end; e++) {
        int s = g_csr_src[e];
        float w = dv * g_dinv[s];
        const float* hs = hin + (size_t)s * C + lane * V;
        if constexpr (V == 4) {
            float4 v = *(const float4*)hs;
            acc[0] += v.x * w; acc[1] += v.y * w; acc[2] += v.z * w; acc[3] += v.w * w;
        } else {
            float2 v = *(const float2*)hs;
            acc[0] += v.x * w; acc[1] += v.y * w;
        }
    }

    const float* bp = bias + lane * V;
    float* op = out + (size_t)gw * C + lane * V;
    if constexpr (V == 4) {
        float4 b = *(const float4*)bp;
        float4 o = make_float4(acc[0] + b.x, acc[1] + b.y, acc[2] + b.z, acc[3] + b.w);
        if (RELU) {
            o.x = fmaxf(o.x, 0.f); o.y = fmaxf(o.y, 0.f);
            o.z = fmaxf(o.z, 0.f); o.w = fmaxf(o.w, 0.f);
        }
        *(float4*)op = o;
    } else {
        float2 b = *(const float2*)bp;
        float2 o = make_float2(acc[0] + b.x, acc[1] + b.y);
        if (RELU) { o.x = fmaxf(o.x, 0.f); o.y = fmaxf(o.y, 0.f); }
        *(float2*)op = o;
    }
}

extern "C" void kernel_launch(void* const* d_in, const int* in_sizes, int n_in,
                              void* d_out, int out_size)
{
    const float* x  = (const float*)d_in[0];
    const void*  ei = d_in[1];
    const float* W1 = (const float*)d_in[2];
    const float* b1 = (const float*)d_in[3];
    const float* W2 = (const float*)d_in[4];
    const float* b2 = (const float*)d_in[5];
    float* out = (float*)d_out;

    float *h1, *a1, *h2;
    int* cnt;
    cudaGetSymbolAddress((void**)&h1, g_h1);
    cudaGetSymbolAddress((void**)&a1, g_a1);
    cudaGetSymbolAddress((void**)&h2, g_h2);
    cudaGetSymbolAddress((void**)&cnt, g_cnt);

    const int EB = (EE + 255) / 256;

    detect_kernel<<<1, 32>>>((const int*)ei);
    cudaMemsetAsync(cnt, 0, NN * sizeof(int));
    count_kernel<<<EB, 256>>>(ei);
    bsum_kernel<<<SCAN_B, 256>>>();
    bscan_kernel<<<1, 256>>>();
    emit_kernel<<<SCAN_B, 256>>>();     // row_start + fill + dinv
    fill_kernel<<<EB, 256>>>(ei);

    // layer 1: h1 = x @ W1 ; a1 = relu(agg(h1) + b1)
    gemm_kernel<INC, HIDC><<<(NN + 63) / 64, 256>>>(x, W1, h1, NN);
    agg_kernel<HIDC, true><<<(NN * 32 + 255) / 256, 256>>>(h1, b1, a1);

    // layer 2: h2 = a1 @ W2 ; out = agg(h2) + b2
    gemm_kernel<HIDC, OUTC><<<(NN + 63) / 64, 256>>>(a1, W2, h2, NN);
    agg_kernel<OUTC, false><<<(NN * 32 + 255) / 256, 256>>>(h2, b2, out);
}

// round 11
// speedup vs baseline: 2.4635x; 1.1826x over previous
#include <cuda_runtime.h>
#include <cuda_bf16.h>
#include <cstdint>

#define NN   50000
#define EE   800000
#define INC  256
#define HIDC 128
#define OUTC 64

#define SCAN_B 196            // scan blocks (196*256 = 50176 >= NN)

typedef unsigned long long ull;

// ---- scratch (no allocs allowed -> device globals) ----
__device__ float g_dinv[NN];
__device__ int   g_cnt[NN];
__device__ int   g_row_start[NN + 1];
__device__ int   g_fill[NN];
__device__ int   g_csr_src[EE];
__device__ int   g_bsum[SCAN_B];
__device__ int   g_boff[SCAN_B];
__device__ float g_h1[NN * HIDC];
__device__ float g_h2[NN * OUTC];
__device__ int   g_is64;

// bf16 hi/lo prepped operands
__device__ __nv_bfloat16 g_xhi[NN * INC];
__device__ __nv_bfloat16 g_xlo[NN * INC];
__device__ __nv_bfloat16 g_w1thi[HIDC * INC];   // W1^T [HIDC][INC]
__device__ __nv_bfloat16 g_w1tlo[HIDC * INC];
__device__ __nv_bfloat16 g_a1hi[NN * HIDC];
__device__ __nv_bfloat16 g_a1lo[NN * HIDC];
__device__ __nv_bfloat16 g_w2thi[OUTC * HIDC];  // W2^T [OUTC][HIDC]
__device__ __nv_bfloat16 g_w2tlo[OUTC * HIDC];

// ============ helpers ============
__device__ __forceinline__ uint32_t smem_u32(const void* p) {
    uint32_t a;
    asm("{ .reg .u64 t; cvta.to.shared.u64 t, %1; cvt.u32.u64 %0, t; }" : "=r"(a) : "l"(p));
    return a;
}
#define SWZ128(b) ((b) ^ (((b) >> 3) & 0x70))

__device__ __forceinline__ void ldsm_x4(uint32_t* r, uint32_t addr) {
    asm volatile("ldmatrix.sync.aligned.m8n8.x4.shared.b16 {%0,%1,%2,%3}, [%4];"
                 : "=r"(r[0]), "=r"(r[1]), "=r"(r[2]), "=r"(r[3]) : "r"(addr));
}
__device__ __forceinline__ void mma_bf16(float* d, const uint32_t* a, const uint32_t* b) {
    asm volatile(
        "mma.sync.aligned.m16n8k16.row.col.f32.bf16.bf16.f32 "
        "{%0,%1,%2,%3}, {%4,%5,%6,%7}, {%8,%9}, {%0,%1,%2,%3};"
        : "+f"(d[0]), "+f"(d[1]), "+f"(d[2]), "+f"(d[3])
        : "r"(a[0]), "r"(a[1]), "r"(a[2]), "r"(a[3]), "r"(b[0]), "r"(b[1]));
}

// ---- detect whether edge_index is int64 or int32 ----
__global__ void detect_kernel(const int* __restrict__ p) {
    if (threadIdx.x == 0 && blockIdx.x == 0) {
        int ok = 1;
        for (int i = 0; i < 64; i++) {
            int lo = p[2 * i], hi = p[2 * i + 1];
            if (hi != 0 || (unsigned)lo >= (unsigned)NN) { ok = 0; break; }
        }
        g_is64 = ok;
    }
}

__device__ __forceinline__ int edge_at(const void* e, long long pos, int is64) {
    if (is64) return (int)((const long long*)e)[pos];
    return ((const int*)e)[pos];
}

__global__ void count_kernel(const void* __restrict__ eidx) {
    int e = blockIdx.x * blockDim.x + threadIdx.x;
    if (e < EE) {
        int is64 = g_is64;
        int d = edge_at(eidx, (long long)EE + e, is64);
        atomicAdd(&g_cnt[d], 1);
    }
}

// ===== 3-phase parallel scan =====
__global__ void __launch_bounds__(256) bsum_kernel() {
    __shared__ int wsum[8];
    int i = blockIdx.x * 256 + threadIdx.x;
    int v = (i < NN) ? g_cnt[i] : 0;
    int s = v;
    #pragma unroll
    for (int o = 16; o > 0; o >>= 1) s += __shfl_down_sync(0xffffffffu, s, o);
    int lane = threadIdx.x & 31, w = threadIdx.x >> 5;
    if (lane == 0) wsum[w] = s;
    __syncthreads();
    if (w == 0) {
        int t = (lane < 8) ? wsum[lane] : 0;
        #pragma unroll
        for (int o = 4; o > 0; o >>= 1) t += __shfl_down_sync(0xffffffffu, t, o);
        if (lane == 0) g_bsum[blockIdx.x] = t;
    }
}

__global__ void __launch_bounds__(256) bscan_kernel() {
    __shared__ int wtot[8];
    int tid = threadIdx.x;
    int v = (tid < SCAN_B) ? g_bsum[tid] : 0;
    int lane = tid & 31, w = tid >> 5;
    int inc = v;
    #pragma unroll
    for (int o = 1; o < 32; o <<= 1) {
        int t = __shfl_up_sync(0xffffffffu, inc, o);
        if (lane >= o) inc += t;
    }
    if (lane == 31) wtot[w] = inc;
    __syncthreads();
    int wo = 0;
    #pragma unroll
    for (int j = 0; j < 8; j++) if (j < w) wo += wtot[j];
    if (tid < SCAN_B) g_boff[tid] = wo + inc - v;
}

__global__ void __launch_bounds__(256) emit_kernel() {
    __shared__ int wtot[8];
    int tid = threadIdx.x;
    int i = blockIdx.x * 256 + tid;
    int v = (i < NN) ? g_cnt[i] : 0;
    int lane = tid & 31, w = tid >> 5;
    int inc = v;
    #pragma unroll
    for (int o = 1; o < 32; o <<= 1) {
        int t = __shfl_up_sync(0xffffffffu, inc, o);
        if (lane >= o) inc += t;
    }
    if (lane == 31) wtot[w] = inc;
    __syncthreads();
    int wo = 0;
    #pragma unroll
    for (int j = 0; j < 8; j++) if (j < w) wo += wtot[j];
    if (i < NN) {
        int excl = g_boff[blockIdx.x] + wo + inc - v;
        g_row_start[i] = excl;
        g_fill[i] = excl;
        g_dinv[i] = rsqrtf((float)(v + 1));
    }
    if (i == 0) g_row_start[NN] = EE;
}

__global__ void fill_kernel(const void* __restrict__ eidx) {
    int e = blockIdx.x * blockDim.x + threadIdx.x;
    if (e < EE) {
        int is64 = g_is64;
        int s = edge_at(eidx, (long long)e, is64);
        int d = edge_at(eidx, (long long)EE + e, is64);
        int pos = atomicAdd(&g_fill[d], 1);
        g_csr_src[pos] = s;
    }
}

// ===== bf16 hi/lo conversion =====
__device__ __forceinline__ void split_bf16(float a, __nv_bfloat16& h, __nv_bfloat16& l) {
    h = __float2bfloat16_rn(a);
    l = __float2bfloat16_rn(a - __bfloat162float(h));
}

__global__ void __launch_bounds__(256) convert_x_kernel(
    const float* __restrict__ x, __nv_bfloat16* __restrict__ hi,
    __nv_bfloat16* __restrict__ lo, int n4)
{
    int i = blockIdx.x * 256 + threadIdx.x;
    if (i >= n4) return;
    float4 a = ((const float4*)x)[i];
    __nv_bfloat16 h[4], l[4];
    split_bf16(a.x, h[0], l[0]); split_bf16(a.y, h[1], l[1]);
    split_bf16(a.z, h[2], l[2]); split_bf16(a.w, h[3], l[3]);
    uint2 uh, ul;
    uh.x = (uint32_t)__bfloat16_as_ushort(h[0]) | ((uint32_t)__bfloat16_as_ushort(h[1]) << 16);
    uh.y = (uint32_t)__bfloat16_as_ushort(h[2]) | ((uint32_t)__bfloat16_as_ushort(h[3]) << 16);
    ul.x = (uint32_t)__bfloat16_as_ushort(l[0]) | ((uint32_t)__bfloat16_as_ushort(l[1]) << 16);
    ul.y = (uint32_t)__bfloat16_as_ushort(l[2]) | ((uint32_t)__bfloat16_as_ushort(l[3]) << 16);
    ((uint2*)hi)[i] = uh;
    ((uint2*)lo)[i] = ul;
}

// W [K][N] -> W^T hi/lo [N][K]
__global__ void __launch_bounds__(256) convert_wt_kernel(
    const float* __restrict__ W, __nv_bfloat16* __restrict__ thi,
    __nv_bfloat16* __restrict__ tlo, int K, int N)
{
    int i = blockIdx.x * 256 + threadIdx.x;
    if (i >= K * N) return;
    int k = i / N, n = i % N;
    __nv_bfloat16 h, l;
    split_bf16(W[i], h, l);
    thi[n * K + k] = h;
    tlo[n * K + k] = l;
}

// ===== bf16-split mma.sync GEMM: C[M,NC] = A[M,KC] @ Bt^T  (Bt is [NC][KC]) =====
// acc = Ah*Bh + Ah*Bl + Al*Bh   (Al*Bl ~ 2^-18, dropped)
template <int KC, int NC>
__global__ void __launch_bounds__(256) mma_gemm_kernel(
    const __nv_bfloat16* __restrict__ Ahi, const __nv_bfloat16* __restrict__ Alo,
    const __nv_bfloat16* __restrict__ Bhi, const __nv_bfloat16* __restrict__ Blo,
    float* __restrict__ C, int M)
{
    extern __shared__ char dsm[];
    constexpr int BK = 64;               // K per chunk: 128B bf16 rows (SW128)
    constexpr int AT = 128 * 128;        // A plane bytes (128 rows x 128B)
    constexpr int BT = NC * 128;         // B plane bytes
    constexpr int SM_AHI = 0, SM_ALO = AT, SM_BHI = 2 * AT, SM_BLO = 2 * AT + BT;

    constexpr int WARPS_M = (NC == 128) ? 2 : 4;
    constexpr int WARPS_N = 8 / WARPS_M;
    constexpr int WM = 128 / WARPS_M;    // 64 / 32
    constexpr int WN = NC / WARPS_N;     // 32 / 32
    constexpr int MT = WM / 16;          // 4 / 2
    constexpr int NG = WN / 16;          // n16 groups: 2 / 2

    uint32_t sb = smem_u32(dsm);
    int tid = threadIdx.x, wid = tid >> 5, lane = tid & 31;
    int warp_m = wid % WARPS_M, warp_n = wid / WARPS_M;
    int bm = blockIdx.x * 128;

    float acc[MT][2 * NG][4];
    #pragma unroll
    for (int im = 0; im < MT; im++)
        #pragma unroll
        for (int jn = 0; jn < 2 * NG; jn++)
            #pragma unroll
            for (int r = 0; r < 4; r++) acc[im][jn][r] = 0.f;

    // ldmatrix lane->row mapping (A): lanes 0-7 rows 0-7, 8-15 rows 8-15,
    // 16-23 rows 0-7 (k+8), 24-31 rows 8-15 (k+8)
    int arow = warp_m * WM + (lane & 7) + ((lane >> 3) & 1) * 8;
    uint32_t aswz = (uint32_t)((arow & 7) << 4);
    uint32_t akc0 = (uint32_t)(((lane >> 4) & 1) * 16);   // k-half byte offset
    // B mapping: lanes 0-7 n-rows 0-7 (k0), 8-15 n 0-7 (k+8), 16-23 n 8-15 (k0), 24-31 n 8-15 (k+8)
    int brow = warp_n * WN + (lane & 7) + ((lane >> 4) & 1) * 8;
    uint32_t bswz = (uint32_t)((brow & 7) << 4);
    uint32_t bkc0 = (uint32_t)(((lane >> 3) & 1) * 16);

    constexpr int NCH = KC / BK;
    #pragma unroll 1
    for (int ch = 0; ch < NCH; ch++) {
        int k0 = ch * BK;
        // ---- stage A planes: 1024 x 16B units each, 4 per thread per plane ----
        #pragma unroll
        for (int i = 0; i < 4; i++) {
            int u = tid + i * 256;
            int row = u >> 3, uc = u & 7;
            uint4 vh = make_uint4(0, 0, 0, 0), vl = make_uint4(0, 0, 0, 0);
            if (bm + row < M) {
                size_t go = (size_t)(bm + row) * KC + k0 + uc * 8;
                vh = *(const uint4*)(Ahi + go);
                vl = *(const uint4*)(Alo + go);
            }
            uint32_t off = SWZ128((uint32_t)(row * 128 + uc * 16));
            *(uint4*)(dsm + SM_AHI + off) = vh;
            *(uint4*)(dsm + SM_ALO + off) = vl;
        }
        // ---- stage B planes: NC*8 units each ----
        #pragma unroll
        for (int i = 0; i < (NC * 8) / 256; i++) {
            int u = tid + i * 256;
            int row = u >> 3, uc = u & 7;
            size_t go = (size_t)row * KC + k0 + uc * 8;
            uint4 vh = *(const uint4*)(Bhi + go);
            uint4 vl = *(const uint4*)(Blo + go);
            uint32_t off = SWZ128((uint32_t)(row * 128 + uc * 16));
            *(uint4*)(dsm + SM_BHI + off) = vh;
            *(uint4*)(dsm + SM_BLO + off) = vl;
        }
        __syncthreads();

        // ---- compute: 4 k16 steps ----
        #pragma unroll
        for (int kt = 0; kt < BK / 16; kt++) {
            uint32_t akc = (uint32_t)(kt * 32) + akc0;
            uint32_t bkc = (uint32_t)(kt * 32) + bkc0;
            uint32_t ah[MT][4], al[MT][4];
            #pragma unroll
            for (int im = 0; im < MT; im++) {
                uint32_t ro = (uint32_t)((arow + im * 16) * 128) + (akc ^ aswz);
                ldsm_x4(ah[im], sb + SM_AHI + ro);
                ldsm_x4(al[im], sb + SM_ALO + ro);
            }
            #pragma unroll
            for (int jg = 0; jg < NG; jg++) {
                uint32_t bh[4], bl[4];
                uint32_t ro = (uint32_t)((brow + jg * 16) * 128) + (bkc ^ bswz);
                ldsm_x4(bh, sb + SM_BHI + ro);
                ldsm_x4(bl, sb + SM_BLO + ro);
                #pragma unroll
                for (int im = 0; im < MT; im++) {
                    mma_bf16(acc[im][2 * jg + 0], ah[im], bh + 0);
                    mma_bf16(acc[im][2 * jg + 0], ah[im], bl + 0);
                    mma_bf16(acc[im][2 * jg + 0], al[im], bh + 0);
                    mma_bf16(acc[im][2 * jg + 1], ah[im], bh + 2);
                    mma_bf16(acc[im][2 * jg + 1], ah[im], bl + 2);
                    mma_bf16(acc[im][2 * jg + 1], al[im], bh + 2);
                }
            }
        }
        __syncthreads();
    }

    // ---- epilogue ----
    int g = lane >> 2, tg = lane & 3;
    #pragma unroll
    for (int im = 0; im < MT; im++) {
        #pragma unroll
        for (int jn = 0; jn < 2 * NG; jn++) {
            int m0 = bm + warp_m * WM + im * 16 + g;
            int n  = warp_n * WN + jn * 8 + tg * 2;
            if (m0 < M)
                *(float2*)(C + (size_t)m0 * NC + n) =
                    make_float2(acc[im][jn][0], acc[im][jn][1]);
            if (m0 + 8 < M)
                *(float2*)(C + (size_t)(m0 + 8) * NC + n) =
                    make_float2(acc[im][jn][2], acc[im][jn][3]);
        }
    }
}

// ===== CSR aggregation: one warp per destination node =====
// OUTM: 0 = f32 out (+bias), 1 = bf16 hi/lo out (+bias, relu)
template <int C, int OUTM>
__global__ void __launch_bounds__(256) agg_kernel(
    const float* __restrict__ hin, const float* __restrict__ bias,
    float* __restrict__ outf, __nv_bfloat16* __restrict__ ohi,
    __nv_bfloat16* __restrict__ olo)
{
    int gw   = (blockIdx.x * blockDim.x + threadIdx.x) >> 5;
    int lane = threadIdx.x & 31;
    if (gw >= NN) return;
    constexpr int V = C / 32;

    float dv = g_dinv[gw];
    float acc[V];
    {
        float w = dv * dv;
        const float* hr = hin + (size_t)gw * C + lane * V;
        if constexpr (V == 4) {
            float4 v = *(const float4*)hr;
            acc[0] = v.x * w; acc[1] = v.y * w; acc[2] = v.z * w; acc[3] = v.w * w;
        } else {
            float2 v = *(const float2*)hr;
            acc[0] = v.x * w; acc[1] = v.y * w;
        }
    }

    int beg = g_row_start[gw], end = g_row_start[gw + 1];
    for (int e = beg; e < end; e++) {
        int s = g_csr_src[e];
        float w = dv * g_dinv[s];
        const float* hs = hin + (size_t)s * C + lane * V;
        if constexpr (V == 4) {
            float4 v = *(const float4*)hs;
            acc[0] += v.x * w; acc[1] += v.y * w; acc[2] += v.z * w; acc[3] += v.w * w;
        } else {
            float2 v = *(const float2*)hs;
            acc[0] += v.x * w; acc[1] += v.y * w;
        }
    }

    const float* bp = bias + lane * V;
    #pragma unroll
    for (int c = 0; c < V; c++) acc[c] += bp[c];

    if constexpr (OUTM == 0) {
        float* op = outf + (size_t)gw * C + lane * V;
        if constexpr (V == 4)
            *(float4*)op = make_float4(acc[0], acc[1], acc[2], acc[3]);
        else
            *(float2*)op = make_float2(acc[0], acc[1]);
    } else {
        __nv_bfloat16 h[V], l[V];
        #pragma unroll
        for (int c = 0; c < V; c++) {
            float o = fmaxf(acc[c], 0.f);
            split_bf16(o, h[c], l[c]);
        }
        size_t o0 = (size_t)gw * C + lane * V;
        if constexpr (V == 4) {
            uint2 uh, ul;
            uh.x = (uint32_t)__bfloat16_as_ushort(h[0]) | ((uint32_t)__bfloat16_as_ushort(h[1]) << 16);
            uh.y = (uint32_t)__bfloat16_as_ushort(h[2]) | ((uint32_t)__bfloat16_as_ushort(h[3]) << 16);
            ul.x = (uint32_t)__bfloat16_as_ushort(l[0]) | ((uint32_t)__bfloat16_as_ushort(l[1]) << 16);
            ul.y = (uint32_t)__bfloat16_as_ushort(l[2]) | ((uint32_t)__bfloat16_as_ushort(l[3]) << 16);
            *(uint2*)(ohi + o0) = uh;
            *(uint2*)(olo + o0) = ul;
        } else {
            uint32_t uh = (uint32_t)__bfloat16_as_ushort(h[0]) | ((uint32_t)__bfloat16_as_ushort(h[1]) << 16);
            uint32_t ul = (uint32_t)__bfloat16_as_ushort(l[0]) | ((uint32_t)__bfloat16_as_ushort(l[1]) << 16);
            *(uint32_t*)(ohi + o0) = uh;
            *(uint32_t*)(olo + o0) = ul;
        }
    }
}

extern "C" void kernel_launch(void* const* d_in, const int* in_sizes, int n_in,
                              void* d_out, int out_size)
{
    const float* x  = (const float*)d_in[0];
    const void*  ei = d_in[1];
    const float* W1 = (const float*)d_in[2];
    const float* b1 = (const float*)d_in[3];
    const float* W2 = (const float*)d_in[4];
    const float* b2 = (const float*)d_in[5];
    float* out = (float*)d_out;

    float *h1, *h2;
    int* cnt;
    __nv_bfloat16 *xhi, *xlo, *w1thi, *w1tlo, *a1hi, *a1lo, *w2thi, *w2tlo;
    cudaGetSymbolAddress((void**)&h1, g_h1);
    cudaGetSymbolAddress((void**)&h2, g_h2);
    cudaGetSymbolAddress((void**)&cnt, g_cnt);
    cudaGetSymbolAddress((void**)&xhi, g_xhi);
    cudaGetSymbolAddress((void**)&xlo, g_xlo);
    cudaGetSymbolAddress((void**)&w1thi, g_w1thi);
    cudaGetSymbolAddress((void**)&w1tlo, g_w1tlo);
    cudaGetSymbolAddress((void**)&a1hi, g_a1hi);
    cudaGetSymbolAddress((void**)&a1lo, g_a1lo);
    cudaGetSymbolAddress((void**)&w2thi, g_w2thi);
    cudaGetSymbolAddress((void**)&w2tlo, g_w2tlo);

    const int SMEM1 = 2 * 128 * 128 + 2 * HIDC * 128;  // 64KB
    const int SMEM2 = 2 * 128 * 128 + 2 * OUTC * 128;  // 48KB
    cudaFuncSetAttribute(mma_gemm_kernel<INC, HIDC>,
                         cudaFuncAttributeMaxDynamicSharedMemorySize, SMEM1);
    cudaFuncSetAttribute(mma_gemm_kernel<HIDC, OUTC>,
                         cudaFuncAttributeMaxDynamicSharedMemorySize, SMEM2);

    const int EB = (EE + 255) / 256;

    detect_kernel<<<1, 32>>>((const int*)ei);
    cudaMemsetAsync(cnt, 0, NN * sizeof(int));
    count_kernel<<<EB, 256>>>(ei);
    bsum_kernel<<<SCAN_B, 256>>>();
    bscan_kernel<<<1, 256>>>();
    emit_kernel<<<SCAN_B, 256>>>();     // row_start + fill + dinv
    fill_kernel<<<EB, 256>>>(ei);

    // operand prep
    convert_x_kernel<<<(NN * INC / 4 + 255) / 256, 256>>>(x, xhi, xlo, NN * INC / 4);
    convert_wt_kernel<<<(INC * HIDC + 255) / 256, 256>>>(W1, w1thi, w1tlo, INC, HIDC);
    convert_wt_kernel<<<(HIDC * OUTC + 255) / 256, 256>>>(W2, w2thi, w2tlo, HIDC, OUTC);

    const int GB = (NN + 127) / 128;
    const int AB = (NN * 32 + 255) / 256;

    // layer 1: h1 = x @ W1 ; a1(hi/lo) = relu(agg(h1) + b1)
    mma_gemm_kernel<INC, HIDC><<<GB, 256, SMEM1>>>(xhi, xlo, w1thi, w1tlo, h1, NN);
    agg_kernel<HIDC, 1><<<AB, 256>>>(h1, b1, nullptr, a1hi, a1lo);

    // layer 2: h2 = a1 @ W2 ; out = agg(h2) + b2
    mma_gemm_kernel<HIDC, OUTC><<<GB, 256, SMEM2>>>(a1hi, a1lo, w2thi, w2tlo, h2, NN);
    agg_kernel<OUTC, 0><<<AB, 256>>>(h2, b2, out, nullptr, nullptr);
}